// round 9
// baseline (speedup 1.0000x reference)
#include <cuda_runtime.h>
#include <cuda_fp16.h>

// CapsuleLayer dynamic routing, fused single kernel, round 8.
// x: [B=64, Cin=8, R=800] fp32 ; W: [NC=128, R=800, Cin=8, O=16] fp32
// out: [B=64, O=16, NC=128] fp32
//
// R8 (structure = R7, G=4, 1 CTA/SM):
//   (1) explicit register double-buffer of W across group iterations
//       (hides L2 latency the compiler wasn't covering at 96 regs).
//   (2) FFMA2 via PTX fma.rn.f32x2 (only reachable from PTX): phase-1
//       accumulators packed as (g0,g1)/(g2,g3) f32x2 pairs -> FMA issue
//       slots halved; also used in phase-2 dots. Exact fp32 math.

namespace {

constexpr int kB    = 64;
constexpr int kCin  = 8;
constexpr int kR    = 800;
constexpr int kNC   = 128;
constexpr int kO    = 16;
constexpr int kG    = 4;
constexpr int kT    = 512;
constexpr int kBPC  = kB / kG;        // 16 CTAs per capsule
constexpr int kWRow = kCin * kO;

struct Smem {
    __half2 prio[kG][kR][kO / 2];     // 102400 B
    __half  xsh[kG][kR][kCin];        //  51200 B (16B rows)
    float   sred[kG][16][kO];         //   4096 B
    float   zred[kG][16];             //    256 B
    float   v[kG][kO];                //    256 B
};

using u64 = unsigned long long;

__device__ __forceinline__ u64 pk2(float lo, float hi) {
    u64 r; asm("mov.b64 %0, {%1, %2};" : "=l"(r) : "f"(lo), "f"(hi)); return r;
}
__device__ __forceinline__ float2 upk2(u64 v) {
    float2 f; asm("mov.b64 {%0, %1}, %2;" : "=f"(f.x), "=f"(f.y) : "l"(v)); return f;
}
__device__ __forceinline__ u64 ffma2(u64 a, u64 b, u64 c) {
    u64 d; asm("fma.rn.f32x2 %0, %1, %2, %3;" : "=l"(d) : "l"(a), "l"(b), "l"(c)); return d;
}
__device__ __forceinline__ u64 fadd2(u64 a, u64 b) {
    u64 d; asm("add.rn.f32x2 %0, %1, %2;" : "=l"(d) : "l"(a), "l"(b)); return d;
}

// exp(x) entirely on fma/alu pipes. Valid for |x| < ~88 (inputs bounded ~50).
__device__ __forceinline__ float fast_exp(float x) {
    const float t  = fmaf(x, 1.44269504f, 12582912.0f);
    const float fi = t - 12582912.0f;
    const float f  = fmaf(x, 1.44269504f, -fi);
    float p = 1.54035304e-4f;
    p = fmaf(p, f, 1.33335581e-3f);
    p = fmaf(p, f, 9.61812911e-3f);
    p = fmaf(p, f, 5.55041087e-2f);
    p = fmaf(p, f, 2.40226507e-1f);
    p = fmaf(p, f, 6.93147182e-1f);
    p = fmaf(p, f, 1.0f);
    const int ii = __float_as_int(t) - 0x4B400000;
    return __int_as_float(__float_as_int(p) + (ii << 23));
}

} // namespace

__global__ __launch_bounds__(kT, 1)
void caps_route_kernel(const float* __restrict__ x,
                       const float* __restrict__ W,
                       float* __restrict__ out) {
    extern __shared__ char smem_raw[];
    Smem* S = reinterpret_cast<Smem*>(smem_raw);

    const int t    = threadIdx.x;
    const int lane = t & 31;
    const int warp = t >> 5;
    const int c    = blockIdx.x / kBPC;
    const int b0   = (blockIdx.x % kBPC) * kG;
    const float* Wc = W + (size_t)c * (kR * kWRow);

    // ---- stage x as fp16 rows: xsh[g][r][i], one row = 16B ----
    for (int rowIdx = t; rowIdx < kG * kR; rowIdx += kT) {
        const int g = rowIdx / kR;
        const int r = rowIdx - g * kR;
        const float* src = x + (size_t)(b0 + g) * (kCin * kR) + r;
        union { __half2 h[4]; uint4 u; } cv;
        #pragma unroll
        for (int k = 0; k < 4; k++)
            cv.h[k] = __floats2half2_rn(src[(2 * k) * kR], src[(2 * k + 1) * kR]);
        *reinterpret_cast<uint4*>(&S->xsh[g][r][0]) = cv.u;
    }
    __syncthreads();

    // ---- phase 1: priors + fused uniform (it=0) s-sum, W prefetch, FFMA2 ----
    // lane = (rr:3 | oq:2): 8 rows x 4 o-quads per warp-iteration.
    {
        const int oq = lane & 3;
        const int rr = lane >> 2;
        const int nGrp = kR / 8;          // 100
        const float4* wbase = reinterpret_cast<const float4*>(Wc);

        u64 ss[2][4];                      // (g-pair, o-comp) running sums
        #pragma unroll
        for (int pr = 0; pr < 2; pr++)
            #pragma unroll
            for (int j = 0; j < 4; j++) ss[pr][j] = pk2(0.f, 0.f);

        int grp = warp;
        float4 w[8];
        {
            const float4* p = wbase + (size_t)(grp * 8 + rr) * 32 + oq;
            #pragma unroll
            for (int i = 0; i < 8; i++) w[i] = __ldg(p + i * 4);
        }

        while (grp < nGrp) {
            const int ngrp = grp + kT / 32;
            const int pgrp = (ngrp < nGrp) ? ngrp : grp;   // dummy reload on tail
            float4 wn[8];
            {
                const float4* p = wbase + (size_t)(pgrp * 8 + rr) * 32 + oq;
                #pragma unroll
                for (int i = 0; i < 8; i++) wn[i] = __ldg(p + i * 4);
            }

            const int r = grp * 8 + rr;
            union { uint4 u; __half2 h[4]; } xa[kG];
            #pragma unroll
            for (int g = 0; g < kG; g++)
                xa[g].u = *reinterpret_cast<const uint4*>(&S->xsh[g][r][0]);

            u64 acc[2][4];
            #pragma unroll
            for (int pr = 0; pr < 2; pr++)
                #pragma unroll
                for (int j = 0; j < 4; j++) acc[pr][j] = pk2(0.f, 0.f);

            #pragma unroll
            for (int k = 0; k < 4; k++) {
                const float2 f0 = __half22float2(xa[0].h[k]);
                const float2 f1 = __half22float2(xa[1].h[k]);
                const float2 f2 = __half22float2(xa[2].h[k]);
                const float2 f3 = __half22float2(xa[3].h[k]);
                #pragma unroll
                for (int half = 0; half < 2; half++) {
                    const int i = 2 * k + half;
                    const u64 xp0 = half ? pk2(f0.y, f1.y) : pk2(f0.x, f1.x);
                    const u64 xp1 = half ? pk2(f2.y, f3.y) : pk2(f2.x, f3.x);
                    const u64 wx = pk2(w[i].x, w[i].x);
                    const u64 wy = pk2(w[i].y, w[i].y);
                    const u64 wz = pk2(w[i].z, w[i].z);
                    const u64 ww = pk2(w[i].w, w[i].w);
                    acc[0][0] = ffma2(wx, xp0, acc[0][0]);
                    acc[0][1] = ffma2(wy, xp0, acc[0][1]);
                    acc[0][2] = ffma2(wz, xp0, acc[0][2]);
                    acc[0][3] = ffma2(ww, xp0, acc[0][3]);
                    acc[1][0] = ffma2(wx, xp1, acc[1][0]);
                    acc[1][1] = ffma2(wy, xp1, acc[1][1]);
                    acc[1][2] = ffma2(wz, xp1, acc[1][2]);
                    acc[1][3] = ffma2(ww, xp1, acc[1][3]);
                }
            }

            // store priors (fp16) + accumulate uniform sums
            #pragma unroll
            for (int pr = 0; pr < 2; pr++) {
                const float2 c0 = upk2(acc[pr][0]);
                const float2 c1 = upk2(acc[pr][1]);
                const float2 c2 = upk2(acc[pr][2]);
                const float2 c3 = upk2(acc[pr][3]);
                union { __half2 h[2]; uint2 u; } pv;
                pv.h[0] = __floats2half2_rn(c0.x, c1.x);
                pv.h[1] = __floats2half2_rn(c2.x, c3.x);
                *reinterpret_cast<uint2*>(&S->prio[2 * pr][r][oq * 2]) = pv.u;
                pv.h[0] = __floats2half2_rn(c0.y, c1.y);
                pv.h[1] = __floats2half2_rn(c2.y, c3.y);
                *reinterpret_cast<uint2*>(&S->prio[2 * pr + 1][r][oq * 2]) = pv.u;
                #pragma unroll
                for (int j = 0; j < 4; j++) ss[pr][j] = fadd2(ss[pr][j], acc[pr][j]);
            }

            #pragma unroll
            for (int i = 0; i < 8; i++) w[i] = wn[i];
            grp = ngrp;
        }

        // unpack ss -> per-g floats, reduce over rr (lane bits 2..4)
        float ssf[kG][4];
        #pragma unroll
        for (int pr = 0; pr < 2; pr++)
            #pragma unroll
            for (int j = 0; j < 4; j++) {
                const float2 f = upk2(ss[pr][j]);
                ssf[2 * pr][j]     = f.x;
                ssf[2 * pr + 1][j] = f.y;
            }
        #pragma unroll
        for (int s = 4; s <= 16; s <<= 1)
            #pragma unroll
            for (int g = 0; g < kG; g++)
                #pragma unroll
                for (int j = 0; j < 4; j++)
                    ssf[g][j] += __shfl_xor_sync(0xffffffffu, ssf[g][j], s);
        if (rr == 0) {
            #pragma unroll
            for (int g = 0; g < kG; g++)
                *reinterpret_cast<float4*>(&S->sred[g][warp][oq * 4]) =
                    make_float4(ssf[g][0], ssf[g][1], ssf[g][2], ssf[g][3]);
        }
    }
    __syncthreads();

    // ---- it=0 finalize: v0 = squash(sum / R), one warp per g ----
    if (warp < kG && lane < 16) {
        float s = 0.f;
        #pragma unroll
        for (int w = 0; w < 16; w++) s += S->sred[warp][w][lane];
        s *= (1.f / kR);
        float sq = s * s;
        #pragma unroll
        for (int off = 8; off; off >>= 1)
            sq += __shfl_xor_sync(0x0000ffffu, sq, off);
        const float coef = sqrtf(sq) / (1.f + sq);
        S->v[warp][lane] = s * coef;
    }
    __syncthreads();

    // ---- fused routing passes: g per warp-quarter, FFMA2 dots ----
    const int g2 = warp >> 2;             // warps 0-3: g0, ... 12-15: g3
    const int wl = warp & 3;
    const int ho = lane & 1;
    const int rs = wl * 16 + (lane >> 1); // 0..63, stride 64 over r

    #pragma unroll
    for (int pass = 0; pass < 2; pass++) {
        const bool last = (pass == 1);

        u64 vp[4];
        #pragma unroll
        for (int k = 0; k < 4; k++)
            vp[k] = pk2(S->v[g2][ho * 8 + 2 * k], S->v[g2][ho * 8 + 2 * k + 1]);

        float z = 0.f;
        u64 sa2[4];
        #pragma unroll
        for (int k = 0; k < 4; k++) sa2[k] = pk2(0.f, 0.f);

        for (int r = rs; r < kR; r += 64) {
            union { uint4 u; __half2 h[4]; } cv;
            cv.u = *reinterpret_cast<const uint4*>(&S->prio[g2][r][ho * 4]);
            u64 pp[4];
            #pragma unroll
            for (int k = 0; k < 4; k++) {
                const float2 pf = __half22float2(cv.h[k]);
                pp[k] = pk2(pf.x, pf.y);
            }
            u64 dacc = pk2(0.f, 0.f);
            #pragma unroll
            for (int k = 0; k < 4; k++) dacc = ffma2(pp[k], vp[k], dacc);
            const float2 df = upk2(dacc);
            const float dh = df.x + df.y;
            const float d  = dh + __shfl_xor_sync(0xffffffffu, dh, 1);
            const float e  = fast_exp(d);      // logits bounded: |d| < ~50
            z += e;
            const u64 ep = pk2(e, e);
            #pragma unroll
            for (int k = 0; k < 4; k++) sa2[k] = ffma2(ep, pp[k], sa2[k]);
        }
        float sa[8];
        #pragma unroll
        for (int k = 0; k < 4; k++) {
            const float2 f = upk2(sa2[k]);
            sa[2 * k] = f.x; sa[2 * k + 1] = f.y;
        }
        // butterfly over same-parity lanes
        #pragma unroll
        for (int s = 16; s >= 2; s >>= 1) {
            z += __shfl_xor_sync(0xffffffffu, z, s);
            #pragma unroll
            for (int j = 0; j < 8; j++)
                sa[j] += __shfl_xor_sync(0xffffffffu, sa[j], s);
        }
        if (lane < 2) {
            #pragma unroll
            for (int j = 0; j < 8; j++)
                S->sred[g2][wl][lane * 8 + j] = sa[j];
            if (lane == 0) S->zred[g2][wl] = z;
        }
        __syncthreads();

        // cross-warp finalize + squash (one warp per g)
        if (warp < kG && lane < 16) {
            const int g = warp;
            float Z = 0.f, num = 0.f;
            #pragma unroll
            for (int w = 0; w < 4; w++) {
                Z   += S->zred[g][w];
                num += S->sred[g][w][lane];
            }
            const float s = num / Z;
            float sq = s * s;
            #pragma unroll
            for (int off = 8; off; off >>= 1)
                sq += __shfl_xor_sync(0x0000ffffu, sq, off);
            const float coef = sqrtf(sq) / (1.f + sq);
            const float vnew = s * coef;
            if (!last) S->v[g][lane] += vnew;   // vacc = v0 + v1 (linearity)
            else out[(size_t)(b0 + g) * (kO * kNC) + (size_t)lane * kNC + c] = vnew;
        }
        if (!last) __syncthreads();
    }
}

extern "C" void kernel_launch(void* const* d_in, const int* in_sizes, int n_in,
                              void* d_out, int out_size) {
    const float* x = (const float*)d_in[0];            // [64, 8, 800]
    const float* W = (const float*)d_in[1];            // [128, 800, 8, 16]
    float* out = (float*)d_out;                        // [64, 16, 128]

    static_assert(sizeof(Smem) <= 227 * 1024, "smem budget");
    cudaFuncSetAttribute(caps_route_kernel,
                         cudaFuncAttributeMaxDynamicSharedMemorySize,
                         (int)sizeof(Smem));
    caps_route_kernel<<<kNC * kBPC, kT, sizeof(Smem)>>>(x, W, out);
}

// round 10
// speedup vs baseline: 1.4919x; 1.4919x over previous
#include <cuda_runtime.h>
#include <cuda_fp16.h>

// CapsuleLayer dynamic routing, round 9: two kernels, G=8.
// x: [B=64, Cin=8, R=800] fp32 ; W: [NC=128, R=800, Cin=8, O=16] fp32
// out: [B=64, O=16, NC=128] fp32
//
// R9: (1) REVERT R8's FFMA2 (pack/unpack ALU regression).
//     (2) kernel A pre-transposes x into fp16 xT[b][r][i] (__device__
//         scratch) -> main kernel needs no x staging smem.
//     (3) G=8 batch items per CTA (fp16 priors = 204.8KB smem): halves the
//         number of CTAs reading each W[c] -> chip L1 wavefronts -24%.
//     (4) iteration-0 handled as a uniform-weight routing pass (frees 32
//         regs that the fused phase-1 sum used to hold).

namespace {

constexpr int kB    = 64;
constexpr int kCin  = 8;
constexpr int kR    = 800;
constexpr int kNC   = 128;
constexpr int kO    = 16;
constexpr int kG    = 8;
constexpr int kT    = 512;
constexpr int kBPC  = kB / kG;        // 8 CTAs per capsule
constexpr int kWRow = kCin * kO;

struct Smem {
    __half2 prio[kG][kR][kO / 2];     // 204800 B
    float   sred[kG][2][kO];          //   1024 B
    float   zred[kG][2];              //     64 B
    float   v[kG][kO];                //    512 B
};

// exp(x) entirely on fma/alu pipes. Valid for |x| < ~88 (inputs bounded ~50).
__device__ __forceinline__ float fast_exp(float x) {
    const float t  = fmaf(x, 1.44269504f, 12582912.0f);
    const float fi = t - 12582912.0f;
    const float f  = fmaf(x, 1.44269504f, -fi);
    float p = 1.54035304e-4f;
    p = fmaf(p, f, 1.33335581e-3f);
    p = fmaf(p, f, 9.61812911e-3f);
    p = fmaf(p, f, 5.55041087e-2f);
    p = fmaf(p, f, 2.40226507e-1f);
    p = fmaf(p, f, 6.93147182e-1f);
    p = fmaf(p, f, 1.0f);
    const int ii = __float_as_int(t) - 0x4B400000;
    return __int_as_float(__float_as_int(p) + (ii << 23));
}

} // namespace

// fp16 transposed x: xT[b][r][i], 16B rows. 819200 B scratch.
__device__ __align__(128) static __half d_xT[kB * kR * kCin];

__global__ void transpose_x_kernel(const float* __restrict__ x) {
    const int id = blockIdx.x * blockDim.x + threadIdx.x;   // one (b, r) each
    if (id >= kB * kR) return;
    const int b = id / kR;
    const int r = id - b * kR;
    const float* src = x + (size_t)b * (kCin * kR) + r;
    union { __half2 h[4]; uint4 u; } cv;
    #pragma unroll
    for (int k = 0; k < 4; k++)
        cv.h[k] = __floats2half2_rn(src[(2 * k) * kR], src[(2 * k + 1) * kR]);
    *reinterpret_cast<uint4*>(&d_xT[(size_t)id * kCin]) = cv.u;
}

__global__ __launch_bounds__(kT, 1)
void caps_route_kernel(const float* __restrict__ W,
                       float* __restrict__ out) {
    extern __shared__ char smem_raw[];
    Smem* S = reinterpret_cast<Smem*>(smem_raw);

    const int t    = threadIdx.x;
    const int lane = t & 31;
    const int warp = t >> 5;
    const int c    = blockIdx.x / kBPC;
    const int b0   = (blockIdx.x % kBPC) * kG;
    const float* Wc = W + (size_t)c * (kR * kWRow);
    const __half* xT = d_xT + (size_t)b0 * (kR * kCin);

    // ---- phase 1: priors[g][r][o] = sum_i x[g][r][i] * W[c,r,i,o] ----
    // lane = (rr:3 | oq:2): 8 rows x 4 o-quads per warp-iteration.
    {
        const int oq = lane & 3;
        const int rr = lane >> 2;

        for (int grp = warp; grp < kR / 8; grp += kT / 32) {
            const int r = grp * 8 + rr;
            union { uint4 u; __half2 h[4]; } xa[kG];
            #pragma unroll
            for (int g = 0; g < kG; g++)
                xa[g].u = *reinterpret_cast<const uint4*>(xT + ((size_t)g * kR + r) * kCin);

            const float4* wr = reinterpret_cast<const float4*>(Wc + (size_t)r * kWRow) + oq;
            float4 acc[kG];
            #pragma unroll
            for (int g = 0; g < kG; g++) acc[g] = make_float4(0.f, 0.f, 0.f, 0.f);

            #pragma unroll
            for (int k = 0; k < 4; k++) {
                float2 xf[kG];
                #pragma unroll
                for (int g = 0; g < kG; g++) xf[g] = __half22float2(xa[g].h[k]);
                #pragma unroll
                for (int half = 0; half < 2; half++) {
                    const float4 w = __ldg(wr + (2 * k + half) * 4);
                    #pragma unroll
                    for (int g = 0; g < kG; g++) {
                        const float xv = half ? xf[g].y : xf[g].x;
                        acc[g].x = fmaf(w.x, xv, acc[g].x);
                        acc[g].y = fmaf(w.y, xv, acc[g].y);
                        acc[g].z = fmaf(w.z, xv, acc[g].z);
                        acc[g].w = fmaf(w.w, xv, acc[g].w);
                    }
                }
            }
            #pragma unroll
            for (int g = 0; g < kG; g++) {
                union { __half2 h[2]; uint2 u; } pv;
                pv.h[0] = __floats2half2_rn(acc[g].x, acc[g].y);
                pv.h[1] = __floats2half2_rn(acc[g].z, acc[g].w);
                *reinterpret_cast<uint2*>(&S->prio[g][r][oq * 2]) = pv.u;
            }
        }
    }
    __syncthreads();

    // ---- routing: 3 passes over priors (pass 0 = uniform weights) ----
    // 2 warps per g: gw = warp>>1, wl = warp&1. lane = (r-slot:4 | ho:1).
    const int gw = warp >> 1;
    const int wl = warp & 1;
    const int ho = lane & 1;
    const int rs = wl * 16 + (lane >> 1);   // 0..31, stride 32 over r

    #pragma unroll
    for (int pass = 0; pass < 3; pass++) {
        const bool last = (pass == 2);

        float vv[8];
        if (pass > 0) {
            #pragma unroll
            for (int j = 0; j < 8; j++) vv[j] = S->v[gw][ho * 8 + j];
        }

        float z = 0.f, sa[8];
        #pragma unroll
        for (int j = 0; j < 8; j++) sa[j] = 0.f;

        for (int r = rs; r < kR; r += 32) {
            union { uint4 u; __half2 h[4]; } cv;
            cv.u = *reinterpret_cast<const uint4*>(&S->prio[gw][r][ho * 4]);
            float p[8];
            #pragma unroll
            for (int k = 0; k < 4; k++) {
                const float2 pf = __half22float2(cv.h[k]);
                p[2 * k] = pf.x; p[2 * k + 1] = pf.y;
            }
            float e;
            if (pass == 0) {
                e = 1.f / kR;
            } else {
                float dh = 0.f;
                #pragma unroll
                for (int j = 0; j < 8; j++) dh = fmaf(p[j], vv[j], dh);
                const float d = dh + __shfl_xor_sync(0xffffffffu, dh, 1);
                e = fast_exp(d);            // logits bounded: |d| < ~50
            }
            z += e;
            #pragma unroll
            for (int j = 0; j < 8; j++) sa[j] = fmaf(e, p[j], sa[j]);
        }
        // butterfly over same-parity lanes
        #pragma unroll
        for (int s = 16; s >= 2; s >>= 1) {
            z += __shfl_xor_sync(0xffffffffu, z, s);
            #pragma unroll
            for (int j = 0; j < 8; j++)
                sa[j] += __shfl_xor_sync(0xffffffffu, sa[j], s);
        }
        if (lane < 2) {
            #pragma unroll
            for (int j = 0; j < 8; j++)
                S->sred[gw][wl][lane * 8 + j] = sa[j];
            if (lane == 0) S->zred[gw][wl] = z;
        }
        __syncthreads();

        // finalize + squash: one warp per g
        if (warp < kG && lane < 16) {
            const int g = warp;
            const float Z   = S->zred[g][0] + S->zred[g][1];
            const float num = S->sred[g][0][lane] + S->sred[g][1][lane];
            const float s = num / Z;
            float sq = s * s;
            #pragma unroll
            for (int off = 8; off; off >>= 1)
                sq += __shfl_xor_sync(0x0000ffffu, sq, off);
            const float coef = sqrtf(sq) / (1.f + sq);
            const float vnew = s * coef;
            if (last) {
                out[(size_t)(b0 + g) * (kO * kNC) + (size_t)lane * kNC + c] = vnew;
            } else if (pass == 0) {
                S->v[g][lane] = vnew;               // v0
            } else {
                S->v[g][lane] += vnew;              // vacc = v0 + v1 (linearity)
            }
        }
        if (!last) __syncthreads();
    }
}

extern "C" void kernel_launch(void* const* d_in, const int* in_sizes, int n_in,
                              void* d_out, int out_size) {
    const float* x = (const float*)d_in[0];            // [64, 8, 800]
    const float* W = (const float*)d_in[1];            // [128, 800, 8, 16]
    float* out = (float*)d_out;                        // [64, 16, 128]

    transpose_x_kernel<<<(kB * kR + kT - 1) / kT, kT>>>(x);

    static_assert(sizeof(Smem) <= 227 * 1024, "smem budget");
    cudaFuncSetAttribute(caps_route_kernel,
                         cudaFuncAttributeMaxDynamicSharedMemorySize,
                         (int)sizeof(Smem));
    caps_route_kernel<<<kNC * kBPC, kT, sizeof(Smem)>>>(W, out);
}